// round 5
// baseline (speedup 1.0000x reference)
#include <cuda_runtime.h>

// ---------------------------------------------------------------------------
// QSRGAN quantum super-resolution, matrix-folded, split-K f32x2 form.
//   out[g,y,x,k] = s_k^2 / max_{j<16} s_j^2,  s = M_g · e(pixel)
// M_g = rows 0..15 of the 30-gate weight circuit (prep kernel), e = tensor
// product of (1, tan(theta_q/2)) (global cos factor cancels in the ratio).
// f32x2 lanes = (dot index i, i+1): M loaded un-duplicated (no movs),
// e built natively in pairs. Gens 0,1 stream from smem (LDS.128 crossbar),
// gens 2,3 from __constant__ (LDC.128 const port) — both ports overlapped.
// ---------------------------------------------------------------------------

typedef unsigned long long u64;

#define NGEN   4
#define QD     6
#define NQ     5
#define NW     (QD * NQ)
#define KEEP   16
#define DIM    32
#define H2     512
#define W2     512
#define HW     (H2 * W2)
#define NTHREADS_TOTAL (HW / 2)      // 2 pixels per thread
#define ROWU2  (DIM / 4)             // 8 ulonglong2 per 32-float row

__device__    ulonglong2 g_Ms[2 * KEEP * ROWU2];   // gens 0,1 (smem source)
__device__    ulonglong2 g_Mc[2 * KEEP * ROWU2];   // gens 2,3 (const source)
__constant__  ulonglong2 cM  [2 * KEEP * ROWU2];   // 4 KB

// ---------------- packed f32x2 helpers ----------------
static __device__ __forceinline__ u64 pk2(float lo, float hi) {
    u64 r; asm("mov.b64 %0, {%1, %2};" : "=l"(r) : "f"(lo), "f"(hi)); return r;
}
static __device__ __forceinline__ float2 up2(u64 v) {
    float2 r; asm("mov.b64 {%0, %1}, %2;" : "=f"(r.x), "=f"(r.y) : "l"(v)); return r;
}
static __device__ __forceinline__ u64 m2(u64 a, u64 b) {
    u64 d; asm("mul.rn.f32x2 %0, %1, %2;" : "=l"(d) : "l"(a), "l"(b)); return d;
}
static __device__ __forceinline__ u64 f2(u64 a, u64 b, u64 c) {
    u64 d; asm("fma.rn.f32x2 %0, %1, %2, %3;" : "=l"(d) : "l"(a), "l"(b), "l"(c)); return d;
}
static __device__ __forceinline__ float rcpa(float x) {
    float r; asm("rcp.approx.f32 %0, %1;" : "=f"(r) : "f"(x)); return r;
}

// CZ diagonal sign mask (adjacent-qubit CZ ladder)
constexpr unsigned czmask_calc() {
    unsigned m = 0;
    for (int i = 0; i < 32; i++) {
        int p = 0;
        for (int y = 0; y < 4; y++)
            p ^= ((i >> (4 - y)) & 1) & ((i >> (3 - y)) & 1);
        if (p) m |= 1u << i;
    }
    return m;
}
static constexpr unsigned CZM = czmask_calc();

// ---------------- prep: build M_g by simulating the circuit on basis columns ----
__global__ void qsr_prep(const float* __restrict__ qp) {
    int t = threadIdx.x;                 // (g, basis column j)
    if (t >= NGEN * DIM) return;
    int g = t >> 5, j = t & 31;

    float st[DIM];
#pragma unroll
    for (int i = 0; i < DIM; i++) st[i] = 0.0f;
    st[j] = 1.0f;

#pragma unroll 1
    for (int d = 0; d < QD; d++) {
#pragma unroll
        for (int q = 0; q < NQ; q++) {
            float s, c;
            sincosf(0.5f * qp[g * NW + d * NQ + q], &s, &c);
            const int str = 1 << (4 - q);
#pragma unroll
            for (int i = 0; i < DIM; i++) {
                if (!(i & str)) {
                    float a0 = st[i], a1 = st[i + str];
                    st[i]       = c * a0 - s * a1;
                    st[i + str] = s * a0 + c * a1;
                }
            }
        }
#pragma unroll
        for (int i = 0; i < DIM; i++)
            if ((CZM >> i) & 1) st[i] = -st[i];
    }
    // row-major float layout [(g&1)*16 + k][j] == natural consecutive-pair packing
    float* dst = (g < 2) ? (float*)g_Ms : (float*)g_Mc;
#pragma unroll
    for (int k = 0; k < KEEP; k++)
        dst[((g & 1) * KEEP + k) * DIM + j] = st[k];
}

// build e in pairs: P[m] = (E_m, E_m * t4), E_m = t0^a0 t1^a1 t2^a2 t3^a3,
// m = 8a0 + 4a1 + 2a2 + a3  (full index i = 2m + a4; qubit0 = MSB)
static __device__ __forceinline__ void build_pairs(u64* P, const float* t) {
    u64 d0 = pk2(t[0], t[0]), d1 = pk2(t[1], t[1]);
    u64 d2 = pk2(t[2], t[2]), d3 = pk2(t[3], t[3]);
    P[0] = pk2(1.0f, t[4]);
    P[1] = m2(P[0], d3);
#pragma unroll
    for (int m = 0; m < 2; m++) P[2 + m] = m2(P[m], d2);
#pragma unroll
    for (int m = 0; m < 4; m++) P[4 + m] = m2(P[m], d1);
#pragma unroll
    for (int m = 0; m < 8; m++) P[8 + m] = m2(P[m], d0);
}

static __device__ __forceinline__ void epi_store(float* og, const float* sv) {
    float s2[KEEP];
#pragma unroll
    for (int k = 0; k < KEEP; k++) s2[k] = sv[k] * sv[k];
    float m = s2[0];
#pragma unroll
    for (int k = 1; k < KEEP; k++) m = fmaxf(m, s2[k]);
    float r = rcpa(m);
#pragma unroll
    for (int c = 0; c < 4; c++) {
        float4 o = make_float4(s2[4*c+0] * r, s2[4*c+1] * r,
                               s2[4*c+2] * r, s2[4*c+3] * r);
        reinterpret_cast<float4*>(og)[c] = o;
    }
}

// ---------------- main kernel ----------------
__global__ __launch_bounds__(128) void qsr_main(const float* __restrict__ x,
                                                float* __restrict__ out) {
    __shared__ ulonglong2 sM[2 * KEEP * ROWU2];   // 4 KB, gens 0,1
    for (int i = threadIdx.x; i < 2 * KEEP * ROWU2; i += 128) sM[i] = g_Ms[i];
    __syncthreads();

    int t = blockIdx.x * 128 + threadIdx.x;   // 0..131071
    int Y = t >> 8;                           // output row
    int j = t & 255;                          // input col; outputs X=2j (A), 2j+1 (B)

    // --- bilinear (half-pixel centers, edge clamp) ---
    int iy = Y >> 1;
    int y0, y1; float wy0, wy1;
    if (Y & 1) { y0 = iy;                  y1 = (iy + 1 < 256) ? iy + 1 : 255; wy0 = 0.75f; wy1 = 0.25f; }
    else       { y0 = (iy > 0) ? iy - 1 : 0; y1 = iy;                          wy0 = 0.25f; wy1 = 0.75f; }
    int xm = (j > 0) ? j - 1 : 0;
    int xp = (j + 1 < 256) ? j + 1 : 255;

    const float* r0 = x + (size_t)(y0 * 256) * NQ;
    const float* r1 = x + (size_t)(y1 * 256) * NQ;

    float tA[NQ], tB[NQ];      // tan(theta/2) per qubit, per pixel
#pragma unroll
    for (int c = 0; c < NQ; c++) {
        float vm0 = __ldg(r0 + xm * NQ + c), vj0 = __ldg(r0 + j * NQ + c), vp0 = __ldg(r0 + xp * NQ + c);
        float vm1 = __ldg(r1 + xm * NQ + c), vj1 = __ldg(r1 + j * NQ + c), vp1 = __ldg(r1 + xp * NQ + c);
        float rowm = wy0 * vm0 + wy1 * vm1;
        float rowj = wy0 * vj0 + wy1 * vj1;
        float rowp = wy0 * vp0 + wy1 * vp1;
        float angA = 0.25f * rowm + 0.75f * rowj;
        float angB = 0.75f * rowj + 0.25f * rowp;
        float sA, cA, sB, cB;
        __sincosf(0.5f * angA, &sA, &cA);
        __sincosf(0.5f * angB, &sB, &cB);
        tA[c] = sA * rcpa(cA);
        tB[c] = sB * rcpa(cB);
    }

    u64 PA[16], PB[16];
    build_pairs(PA, tA);
    build_pairs(PB, tB);

    size_t pixA = (size_t)(Y * W2 + 2 * j) * 16;

    // two passes: pass gp handles smem gen gp and const gen gp+2 together
    // (interleaved per row so the LDS crossbar and LDC const port overlap)
#pragma unroll 1
    for (int gp = 0; gp < 2; gp++) {
        float sA0[KEEP], sB0[KEEP], sA1[KEEP], sB1[KEEP];
        const int gbase = gp * (KEEP * ROWU2);
#pragma unroll
        for (int k = 0; k < KEEP; k++) {
            const int rb = gbase + k * ROWU2;
            ulonglong2 m0 = sM[rb + 0];
            ulonglong2 n0 = cM[rb + 0];
            u64 aA = m2(m0.x, PA[0]), aB = m2(m0.x, PB[0]);
            u64 bA = m2(n0.x, PA[0]), bB = m2(n0.x, PB[0]);
            aA = f2(m0.y, PA[1], aA); aB = f2(m0.y, PB[1], aB);
            bA = f2(n0.y, PA[1], bA); bB = f2(n0.y, PB[1], bB);
#pragma unroll
            for (int ii = 1; ii < ROWU2; ii++) {
                ulonglong2 mm = sM[rb + ii];
                ulonglong2 nn = cM[rb + ii];
                aA = f2(mm.x, PA[2*ii],   aA);  aB = f2(mm.x, PB[2*ii],   aB);
                aA = f2(mm.y, PA[2*ii+1], aA);  aB = f2(mm.y, PB[2*ii+1], aB);
                bA = f2(nn.x, PA[2*ii],   bA);  bB = f2(nn.x, PB[2*ii],   bB);
                bA = f2(nn.y, PA[2*ii+1], bA);  bB = f2(nn.y, PB[2*ii+1], bB);
            }
            float2 fa = up2(aA); sA0[k] = fa.x + fa.y;
            float2 fb = up2(aB); sB0[k] = fb.x + fb.y;
            float2 ga = up2(bA); sA1[k] = ga.x + ga.y;
            float2 gb = up2(bB); sB1[k] = gb.x + gb.y;
        }
        float* ogs = out + (size_t)gp       * ((size_t)HW * 16) + pixA;
        float* ogc = out + (size_t)(gp + 2) * ((size_t)HW * 16) + pixA;
        epi_store(ogs,      sA0);
        epi_store(ogs + 16, sB0);
        epi_store(ogc,      sA1);
        epi_store(ogc + 16, sB1);
    }
}

extern "C" void kernel_launch(void* const* d_in, const int* in_sizes, int n_in,
                              void* d_out, int out_size) {
    const float* x  = (const float*)d_in[0];   // [256,256,5] f32
    const float* qp = (const float*)d_in[1];   // [4,30] f32
    float* out = (float*)d_out;                // [4,512,512,16] f32

    qsr_prep<<<1, 128>>>(qp);
    void* src = nullptr;
    cudaGetSymbolAddress(&src, g_Mc);
    cudaMemcpyToSymbolAsync(cM, src, sizeof(cM), 0, cudaMemcpyDeviceToDevice, 0);
    qsr_main<<<NTHREADS_TOTAL / 128, 128>>>(x, out);
}

// round 7
// speedup vs baseline: 1.0858x; 1.0858x over previous
#include <cuda_runtime.h>

// ---------------------------------------------------------------------------
// QSRGAN quantum super-resolution, matrix-folded, t4-factored split-K form.
//   out[g,y,x,k] = s_k^2 / max_{j<16} s_j^2,  s = M_g · e(pixel)
//   s_k = dot(Meven[k], E) + t4 * dot(Modd[k], E),  E = 16 monomials of t0..t3
// M rows stored permuted (even cols | odd cols) by the prep kernel so both
// dots are consecutive-pair f32x2 split-K. 2 pixels/thread. Gens 0,1 stream
// from smem (LDS.128), gens 2,3 from __constant__ (LDC.128).
// ---------------------------------------------------------------------------

typedef unsigned long long u64;

#define NGEN   4
#define QD     6
#define NQ     5
#define NW     (QD * NQ)
#define KEEP   16
#define DIM    32
#define H2     512
#define W2     512
#define HW     (H2 * W2)
#define NTHREADS_TOTAL (HW / 2)      // 2 pixels per thread
#define ROWU2  (DIM / 4)             // 8 ulonglong2 per 32-float row

__device__    ulonglong2 g_Ms[2 * KEEP * ROWU2];   // gens 0,1 (smem source), permuted rows
__device__    ulonglong2 g_Mc[2 * KEEP * ROWU2];   // gens 2,3 (const source), permuted rows
__constant__  ulonglong2 cM  [2 * KEEP * ROWU2];   // 4 KB

// ---------------- packed f32x2 helpers ----------------
static __device__ __forceinline__ u64 pk2(float lo, float hi) {
    u64 r; asm("mov.b64 %0, {%1, %2};" : "=l"(r) : "f"(lo), "f"(hi)); return r;
}
static __device__ __forceinline__ float2 up2(u64 v) {
    float2 r; asm("mov.b64 {%0, %1}, %2;" : "=f"(r.x), "=f"(r.y) : "l"(v)); return r;
}
static __device__ __forceinline__ u64 m2(u64 a, u64 b) {
    u64 d; asm("mul.rn.f32x2 %0, %1, %2;" : "=l"(d) : "l"(a), "l"(b)); return d;
}
static __device__ __forceinline__ u64 f2(u64 a, u64 b, u64 c) {
    u64 d; asm("fma.rn.f32x2 %0, %1, %2, %3;" : "=l"(d) : "l"(a), "l"(b), "l"(c)); return d;
}
static __device__ __forceinline__ float rcpa(float x) {
    float r; asm("rcp.approx.f32 %0, %1;" : "=f"(r) : "f"(x)); return r;
}

// CZ diagonal sign mask (adjacent-qubit CZ ladder)
constexpr unsigned czmask_calc() {
    unsigned m = 0;
    for (int i = 0; i < 32; i++) {
        int p = 0;
        for (int y = 0; y < 4; y++)
            p ^= ((i >> (4 - y)) & 1) & ((i >> (3 - y)) & 1);
        if (p) m |= 1u << i;
    }
    return m;
}
static constexpr unsigned CZM = czmask_calc();

// ---------------- prep: simulate circuit on basis columns, write permuted M ----
__global__ void qsr_prep(const float* __restrict__ qp) {
    int t = threadIdx.x;                 // (g, basis column j)
    if (t >= NGEN * DIM) return;
    int g = t >> 5, j = t & 31;

    float st[DIM];
#pragma unroll
    for (int i = 0; i < DIM; i++) st[i] = 0.0f;
    st[j] = 1.0f;

#pragma unroll 1
    for (int d = 0; d < QD; d++) {
#pragma unroll
        for (int q = 0; q < NQ; q++) {
            float s, c;
            sincosf(0.5f * qp[g * NW + d * NQ + q], &s, &c);
            const int str = 1 << (4 - q);
#pragma unroll
            for (int i = 0; i < DIM; i++) {
                if (!(i & str)) {
                    float a0 = st[i], a1 = st[i + str];
                    st[i]       = c * a0 - s * a1;
                    st[i + str] = s * a0 + c * a1;
                }
            }
        }
#pragma unroll
        for (int i = 0; i < DIM; i++)
            if ((CZM >> i) & 1) st[i] = -st[i];
    }
    // permuted row layout: floats [0..15] = even columns, [16..31] = odd columns
    float* dst = (g < 2) ? (float*)g_Ms : (float*)g_Mc;
    int pos = (j & 1) ? 16 + (j >> 1) : (j >> 1);
#pragma unroll
    for (int k = 0; k < KEEP; k++)
        dst[((g & 1) * KEEP + k) * DIM + pos] = st[k];
}

// E monomials of t0..t3 in pairs: EP[m'] = (E_{2m'}, E_{2m'+1} = E_{2m'}*t3),
// E_m = t0^a0 t1^a1 t2^a2 t3^a3, m = 8a0+4a1+2a2+a3
static __device__ __forceinline__ void build_pairs(u64* EP, const float* t) {
    u64 d0 = pk2(t[0], t[0]), d1 = pk2(t[1], t[1]), d2 = pk2(t[2], t[2]);
    EP[0] = pk2(1.0f, t[3]);
    EP[1] = m2(EP[0], d2);
#pragma unroll
    for (int m = 0; m < 2; m++) EP[2 + m] = m2(EP[m], d1);
#pragma unroll
    for (int m = 0; m < 4; m++) EP[4 + m] = m2(EP[m], d0);
}

// ---------------- main kernel ----------------
__global__ __launch_bounds__(128, 4) void qsr_main(const float* __restrict__ x,
                                                   float* __restrict__ out) {
    __shared__ ulonglong2 sM[2 * KEEP * ROWU2];   // 4 KB, gens 0,1
    for (int i = threadIdx.x; i < 2 * KEEP * ROWU2; i += 128) sM[i] = g_Ms[i];

    int t = blockIdx.x * 128 + threadIdx.x;   // 0..131071
    int Y = t >> 8;                           // output row
    int j = t & 255;                          // input col; outputs X=2j (A), 2j+1 (B)

    // --- bilinear (half-pixel centers, edge clamp) ---
    int iy = Y >> 1;
    int y0, y1; float wy0, wy1;
    if (Y & 1) { y0 = iy;                  y1 = (iy + 1 < 256) ? iy + 1 : 255; wy0 = 0.75f; wy1 = 0.25f; }
    else       { y0 = (iy > 0) ? iy - 1 : 0; y1 = iy;                          wy0 = 0.25f; wy1 = 0.75f; }
    int xm = (j > 0) ? j - 1 : 0;
    int xp = (j + 1 < 256) ? j + 1 : 255;

    const float* r0 = x + (size_t)(y0 * 256) * NQ;
    const float* r1 = x + (size_t)(y1 * 256) * NQ;

    float tA[NQ], tB[NQ];      // tan(theta/2) per qubit, per pixel
#pragma unroll
    for (int c = 0; c < NQ; c++) {
        float vm0 = __ldg(r0 + xm * NQ + c), vj0 = __ldg(r0 + j * NQ + c), vp0 = __ldg(r0 + xp * NQ + c);
        float vm1 = __ldg(r1 + xm * NQ + c), vj1 = __ldg(r1 + j * NQ + c), vp1 = __ldg(r1 + xp * NQ + c);
        float rowm = wy0 * vm0 + wy1 * vm1;
        float rowj = wy0 * vj0 + wy1 * vj1;
        float rowp = wy0 * vp0 + wy1 * vp1;
        float angA = 0.25f * rowm + 0.75f * rowj;
        float angB = 0.75f * rowj + 0.25f * rowp;
        float sA, cA, sB, cB;
        __sincosf(0.5f * angA, &sA, &cA);
        __sincosf(0.5f * angB, &sB, &cB);
        tA[c] = sA * rcpa(cA);
        tB[c] = sB * rcpa(cB);
    }

    u64 EPA[8], EPB[8];
    build_pairs(EPA, tA);
    build_pairs(EPB, tB);
    u64 T4A = pk2(tA[4], tA[4]);
    u64 T4B = pk2(tB[4], tB[4]);

    __syncthreads();   // sM ready (placed late: prologue overlapped with loads)

    size_t pixA = (size_t)(Y * W2 + 2 * j) * 16;

#pragma unroll 1
    for (int g = 0; g < NGEN; g++) {
        const bool use_c = (g & 1);            // order: gen0(smem), gen2(const), gen1(smem), gen3(const)
        const int  gsel  = (g >> 1);
        const int  gout  = gsel + (use_c ? 2 : 0);   // TRUE generator index (fixes R6 bug)
        const ulonglong2* Mg = (use_c ? cM : sM) + gsel * (KEEP * ROWU2);

        u64 st2[KEEP];                          // staged (sA^2, sB^2) per k
        float mA = 0.0f, mB = 0.0f;
#pragma unroll
        for (int k = 0; k < KEEP; k++) {
            const ulonglong2* R = Mg + k * ROWU2;   // [0..3]=even cols, [4..7]=odd cols
            ulonglong2 e0 = R[0], e1 = R[1], e2 = R[2], e3 = R[3];
            ulonglong2 o0 = R[4], o1 = R[5], o2 = R[6], o3 = R[7];

            u64 aE = m2(e0.x, EPA[0]);  u64 bE = m2(e0.x, EPB[0]);
            u64 aO = m2(o0.x, EPA[0]);  u64 bO = m2(o0.x, EPB[0]);
            aE = f2(e0.y, EPA[1], aE);  bE = f2(e0.y, EPB[1], bE);
            aO = f2(o0.y, EPA[1], aO);  bO = f2(o0.y, EPB[1], bO);
            aE = f2(e1.x, EPA[2], aE);  bE = f2(e1.x, EPB[2], bE);
            aO = f2(o1.x, EPA[2], aO);  bO = f2(o1.x, EPB[2], bO);
            aE = f2(e1.y, EPA[3], aE);  bE = f2(e1.y, EPB[3], bE);
            aO = f2(o1.y, EPA[3], aO);  bO = f2(o1.y, EPB[3], bO);
            aE = f2(e2.x, EPA[4], aE);  bE = f2(e2.x, EPB[4], bE);
            aO = f2(o2.x, EPA[4], aO);  bO = f2(o2.x, EPB[4], bO);
            aE = f2(e2.y, EPA[5], aE);  bE = f2(e2.y, EPB[5], bE);
            aO = f2(o2.y, EPA[5], aO);  bO = f2(o2.y, EPB[5], bO);
            aE = f2(e3.x, EPA[6], aE);  bE = f2(e3.x, EPB[6], bE);
            aO = f2(o3.x, EPA[6], aO);  bO = f2(o3.x, EPB[6], bO);
            aE = f2(e3.y, EPA[7], aE);  bE = f2(e3.y, EPB[7], bE);
            aO = f2(o3.y, EPA[7], aO);  bO = f2(o3.y, EPB[7], bO);

            u64 cA = f2(T4A, aO, aE);           // (lo,hi) partial sums, pixel A
            u64 cB = f2(T4B, bO, bE);
            float2 fa = up2(cA); float sa = fa.x + fa.y;
            float2 fb = up2(cB); float sb = fb.x + fb.y;
            u64 p  = pk2(sa, sb);
            u64 q  = m2(p, p);                  // (sa^2, sb^2)
            st2[k] = q;
            float2 sq = up2(q);
            mA = fmaxf(mA, sq.x);
            mB = fmaxf(mB, sq.y);
        }

        float rA = rcpa(mA), rB = rcpa(mB);
        u64 RR = pk2(rA, rB);
        float oa[KEEP], ob[KEEP];
#pragma unroll
        for (int k = 0; k < KEEP; k++) {
            float2 o = up2(m2(st2[k], RR));
            oa[k] = o.x; ob[k] = o.y;
        }
        float* og = out + (size_t)gout * ((size_t)HW * 16) + pixA;
#pragma unroll
        for (int c = 0; c < 4; c++) {
            reinterpret_cast<float4*>(og)[c] =
                make_float4(oa[4*c], oa[4*c+1], oa[4*c+2], oa[4*c+3]);
            reinterpret_cast<float4*>(og + 16)[c] =
                make_float4(ob[4*c], ob[4*c+1], ob[4*c+2], ob[4*c+3]);
        }
    }
}

extern "C" void kernel_launch(void* const* d_in, const int* in_sizes, int n_in,
                              void* d_out, int out_size) {
    const float* x  = (const float*)d_in[0];   // [256,256,5] f32
    const float* qp = (const float*)d_in[1];   // [4,30] f32
    float* out = (float*)d_out;                // [4,512,512,16] f32

    qsr_prep<<<1, 128>>>(qp);
    void* src = nullptr;
    cudaGetSymbolAddress(&src, g_Mc);
    cudaMemcpyToSymbolAsync(cM, src, sizeof(cM), 0, cudaMemcpyDeviceToDevice, 0);
    qsr_main<<<NTHREADS_TOTAL / 128, 128>>>(x, out);
}

// round 8
// speedup vs baseline: 1.2842x; 1.1828x over previous
#include <cuda_runtime.h>

// ---------------------------------------------------------------------------
// QSRGAN quantum super-resolution, matrix-folded, t4-factored split-K form.
//   out[g,y,x,k] = s_k^2 / max_{j<16} s_j^2,  s = M_g · e(pixel)
//   s_k = dot(Meven[k], E) + t4 * dot(Modd[k], E),  E = 16 monomials of t0..t3
// Gens 0,1 from __shared__ (true LDS.128), gens 2,3 from __constant__
// (true LDC.128) — separate code paths so no generic-pointer degradation.
// ---------------------------------------------------------------------------

typedef unsigned long long u64;

#define NGEN   4
#define QD     6
#define NQ     5
#define NW     (QD * NQ)
#define KEEP   16
#define DIM    32
#define H2     512
#define W2     512
#define HW     (H2 * W2)
#define NTHREADS_TOTAL (HW / 2)      // 2 pixels per thread
#define ROWU2  (DIM / 4)             // 8 ulonglong2 per 32-float row

__device__    ulonglong2 g_Ms[2 * KEEP * ROWU2];   // gens 0,1 (smem source), permuted rows
__device__    ulonglong2 g_Mc[2 * KEEP * ROWU2];   // gens 2,3 (const source), permuted rows
__constant__  ulonglong2 cM  [2 * KEEP * ROWU2];   // 4 KB

// ---------------- packed f32x2 helpers ----------------
static __device__ __forceinline__ u64 pk2(float lo, float hi) {
    u64 r; asm("mov.b64 %0, {%1, %2};" : "=l"(r) : "f"(lo), "f"(hi)); return r;
}
static __device__ __forceinline__ float2 up2(u64 v) {
    float2 r; asm("mov.b64 {%0, %1}, %2;" : "=f"(r.x), "=f"(r.y) : "l"(v)); return r;
}
static __device__ __forceinline__ u64 m2(u64 a, u64 b) {
    u64 d; asm("mul.rn.f32x2 %0, %1, %2;" : "=l"(d) : "l"(a), "l"(b)); return d;
}
static __device__ __forceinline__ u64 f2(u64 a, u64 b, u64 c) {
    u64 d; asm("fma.rn.f32x2 %0, %1, %2, %3;" : "=l"(d) : "l"(a), "l"(b), "l"(c)); return d;
}
static __device__ __forceinline__ float rcpa(float x) {
    float r; asm("rcp.approx.f32 %0, %1;" : "=f"(r) : "f"(x)); return r;
}

// CZ diagonal sign mask (adjacent-qubit CZ ladder)
constexpr unsigned czmask_calc() {
    unsigned m = 0;
    for (int i = 0; i < 32; i++) {
        int p = 0;
        for (int y = 0; y < 4; y++)
            p ^= ((i >> (4 - y)) & 1) & ((i >> (3 - y)) & 1);
        if (p) m |= 1u << i;
    }
    return m;
}
static constexpr unsigned CZM = czmask_calc();

// ---------------- prep: simulate circuit on basis columns, write permuted M ----
__global__ void qsr_prep(const float* __restrict__ qp) {
    int t = threadIdx.x;                 // (g, basis column j)
    if (t >= NGEN * DIM) return;
    int g = t >> 5, j = t & 31;

    float st[DIM];
#pragma unroll
    for (int i = 0; i < DIM; i++) st[i] = 0.0f;
    st[j] = 1.0f;

#pragma unroll 1
    for (int d = 0; d < QD; d++) {
#pragma unroll
        for (int q = 0; q < NQ; q++) {
            float s, c;
            sincosf(0.5f * qp[g * NW + d * NQ + q], &s, &c);
            const int str = 1 << (4 - q);
#pragma unroll
            for (int i = 0; i < DIM; i++) {
                if (!(i & str)) {
                    float a0 = st[i], a1 = st[i + str];
                    st[i]       = c * a0 - s * a1;
                    st[i + str] = s * a0 + c * a1;
                }
            }
        }
#pragma unroll
        for (int i = 0; i < DIM; i++)
            if ((CZM >> i) & 1) st[i] = -st[i];
    }
    // permuted row layout: floats [0..15] = even columns, [16..31] = odd columns
    float* dst = (g < 2) ? (float*)g_Ms : (float*)g_Mc;
    int pos = (j & 1) ? 16 + (j >> 1) : (j >> 1);
#pragma unroll
    for (int k = 0; k < KEEP; k++)
        dst[((g & 1) * KEEP + k) * DIM + pos] = st[k];
}

// E monomials of t0..t3 in pairs: EP[m'] = (E_{2m'}, E_{2m'+1} = E_{2m'}*t3)
static __device__ __forceinline__ void build_pairs(u64* EP, const float* t) {
    u64 d0 = pk2(t[0], t[0]), d1 = pk2(t[1], t[1]), d2 = pk2(t[2], t[2]);
    EP[0] = pk2(1.0f, t[3]);
    EP[1] = m2(EP[0], d2);
#pragma unroll
    for (int m = 0; m < 2; m++) EP[2 + m] = m2(EP[m], d1);
#pragma unroll
    for (int m = 0; m < 4; m++) EP[4 + m] = m2(EP[m], d0);
}

// One generator: MARR must be a direct array expression (shared or constant)
// so the compiler emits the proper address-space load (LDS.128 / LDC.128).
// Loads staged even-block then odd-block to cap transient registers.
#define GEN_BODY(MARR, GSEL, GOUT)                                            \
    {                                                                         \
        const int gb = (GSEL) * (KEEP * ROWU2);                               \
        u64 st2[KEEP];                                                        \
        float mA = 0.0f, mB = 0.0f;                                           \
        _Pragma("unroll")                                                     \
        for (int k = 0; k < KEEP; k++) {                                      \
            const int rb = gb + k * ROWU2;                                    \
            ulonglong2 r0 = MARR[rb + 0], r1 = MARR[rb + 1];                  \
            ulonglong2 r2 = MARR[rb + 2], r3 = MARR[rb + 3];                  \
            u64 aE = m2(r0.x, EPA[0]);  u64 bE = m2(r0.x, EPB[0]);            \
            aE = f2(r0.y, EPA[1], aE);  bE = f2(r0.y, EPB[1], bE);            \
            aE = f2(r1.x, EPA[2], aE);  bE = f2(r1.x, EPB[2], bE);            \
            aE = f2(r1.y, EPA[3], aE);  bE = f2(r1.y, EPB[3], bE);            \
            aE = f2(r2.x, EPA[4], aE);  bE = f2(r2.x, EPB[4], bE);            \
            aE = f2(r2.y, EPA[5], aE);  bE = f2(r2.y, EPB[5], bE);            \
            aE = f2(r3.x, EPA[6], aE);  bE = f2(r3.x, EPB[6], bE);            \
            aE = f2(r3.y, EPA[7], aE);  bE = f2(r3.y, EPB[7], bE);            \
            r0 = MARR[rb + 4]; r1 = MARR[rb + 5];                             \
            r2 = MARR[rb + 6]; r3 = MARR[rb + 7];                             \
            u64 aO = m2(r0.x, EPA[0]);  u64 bO = m2(r0.x, EPB[0]);            \
            aO = f2(r0.y, EPA[1], aO);  bO = f2(r0.y, EPB[1], bO);            \
            aO = f2(r1.x, EPA[2], aO);  bO = f2(r1.x, EPB[2], bO);            \
            aO = f2(r1.y, EPA[3], aO);  bO = f2(r1.y, EPB[3], bO);            \
            aO = f2(r2.x, EPA[4], aO);  bO = f2(r2.x, EPB[4], bO);            \
            aO = f2(r2.y, EPA[5], aO);  bO = f2(r2.y, EPB[5], bO);            \
            aO = f2(r3.x, EPA[6], aO);  bO = f2(r3.x, EPB[6], bO);            \
            aO = f2(r3.y, EPA[7], aO);  bO = f2(r3.y, EPB[7], bO);            \
            u64 cA = f2(T4A, aO, aE);                                         \
            u64 cB = f2(T4B, bO, bE);                                         \
            float2 fa = up2(cA); float sa = fa.x + fa.y;                      \
            float2 fb = up2(cB); float sb = fb.x + fb.y;                      \
            u64 p = pk2(sa, sb);                                              \
            u64 q = m2(p, p);                                                 \
            st2[k] = q;                                                       \
            float2 sq = up2(q);                                               \
            mA = fmaxf(mA, sq.x);                                             \
            mB = fmaxf(mB, sq.y);                                             \
        }                                                                     \
        u64 RR = pk2(rcpa(mA), rcpa(mB));                                     \
        float* og = out + (size_t)(GOUT) * ((size_t)HW * 16) + pixA;          \
        _Pragma("unroll")                                                     \
        for (int c = 0; c < 4; c++) {                                         \
            float2 o0 = up2(m2(st2[4*c + 0], RR));                            \
            float2 o1 = up2(m2(st2[4*c + 1], RR));                            \
            float2 o2 = up2(m2(st2[4*c + 2], RR));                            \
            float2 o3 = up2(m2(st2[4*c + 3], RR));                            \
            reinterpret_cast<float4*>(og)[c] =                                \
                make_float4(o0.x, o1.x, o2.x, o3.x);                          \
            reinterpret_cast<float4*>(og + 16)[c] =                           \
                make_float4(o0.y, o1.y, o2.y, o3.y);                          \
        }                                                                     \
    }

// ---------------- main kernel ----------------
__global__ __launch_bounds__(128, 4) void qsr_main(const float* __restrict__ x,
                                                   float* __restrict__ out) {
    __shared__ ulonglong2 sM[2 * KEEP * ROWU2];   // 4 KB, gens 0,1
    for (int i = threadIdx.x; i < 2 * KEEP * ROWU2; i += 128) sM[i] = g_Ms[i];

    int t = blockIdx.x * 128 + threadIdx.x;   // 0..131071
    int Y = t >> 8;                           // output row
    int j = t & 255;                          // input col; outputs X=2j (A), 2j+1 (B)

    // --- bilinear (half-pixel centers, edge clamp) ---
    int iy = Y >> 1;
    int y0, y1; float wy0, wy1;
    if (Y & 1) { y0 = iy;                  y1 = (iy + 1 < 256) ? iy + 1 : 255; wy0 = 0.75f; wy1 = 0.25f; }
    else       { y0 = (iy > 0) ? iy - 1 : 0; y1 = iy;                          wy0 = 0.25f; wy1 = 0.75f; }
    int xm = (j > 0) ? j - 1 : 0;
    int xp = (j + 1 < 256) ? j + 1 : 255;

    const float* r0 = x + (size_t)(y0 * 256) * NQ;
    const float* r1 = x + (size_t)(y1 * 256) * NQ;

    float tA[NQ], tB[NQ];      // tan(theta/2) per qubit, per pixel
#pragma unroll
    for (int c = 0; c < NQ; c++) {
        float vm0 = __ldg(r0 + xm * NQ + c), vj0 = __ldg(r0 + j * NQ + c), vp0 = __ldg(r0 + xp * NQ + c);
        float vm1 = __ldg(r1 + xm * NQ + c), vj1 = __ldg(r1 + j * NQ + c), vp1 = __ldg(r1 + xp * NQ + c);
        float rowm = wy0 * vm0 + wy1 * vm1;
        float rowj = wy0 * vj0 + wy1 * vj1;
        float rowp = wy0 * vp0 + wy1 * vp1;
        float angA = 0.25f * rowm + 0.75f * rowj;
        float angB = 0.75f * rowj + 0.25f * rowp;
        float sA, cA, sB, cB;
        __sincosf(0.5f * angA, &sA, &cA);
        __sincosf(0.5f * angB, &sB, &cB);
        tA[c] = sA * rcpa(cA);
        tB[c] = sB * rcpa(cB);
    }

    u64 EPA[8], EPB[8];
    build_pairs(EPA, tA);
    build_pairs(EPB, tB);
    u64 T4A = pk2(tA[4], tA[4]);
    u64 T4B = pk2(tB[4], tB[4]);

    __syncthreads();   // sM ready (placed late: prologue overlapped with loads)

    size_t pixA = (size_t)(Y * W2 + 2 * j) * 16;

    // interleave ports: smem gen0, const gen2, smem gen1, const gen3
    GEN_BODY(sM, 0, 0)
    GEN_BODY(cM, 0, 2)
    GEN_BODY(sM, 1, 1)
    GEN_BODY(cM, 1, 3)
}

extern "C" void kernel_launch(void* const* d_in, const int* in_sizes, int n_in,
                              void* d_out, int out_size) {
    const float* x  = (const float*)d_in[0];   // [256,256,5] f32
    const float* qp = (const float*)d_in[1];   // [4,30] f32
    float* out = (float*)d_out;                // [4,512,512,16] f32

    qsr_prep<<<1, 128>>>(qp);
    void* src = nullptr;
    cudaGetSymbolAddress(&src, g_Mc);
    cudaMemcpyToSymbolAsync(cM, src, sizeof(cM), 0, cudaMemcpyDeviceToDevice, 0);
    qsr_main<<<NTHREADS_TOTAL / 128, 128>>>(x, out);
}